// round 13
// baseline (speedup 1.0000x reference)
#include <cuda_runtime.h>

#define NN 50000
#define EE 800000
#define HH 64
#define NBANK 8

// ---------------- device scratch (no allocation allowed) ----------------
__device__ __align__(16) float g_y[(size_t)NN * HH];
__device__ __align__(16) float g_agg[(size_t)NN * HH];
__device__ __align__(16) float g_u[(size_t)NN * HH];
__device__ double g_sumB[NBANK][HH];       // banked BN column sums
__device__ double g_sqB[NBANK][HH];        // banked BN column sum-squares
__device__ int g_ei32;                     // 1 if edge_index is int32, 0 if int64

// Probe edge_index dtype (int32 vs int64) — see R2 notes. Deterministic.
__global__ void detect_dtype_kernel(const int* __restrict__ ei) {
    if (threadIdx.x == 0) {
        int nz = 0;
#pragma unroll
        for (int i = 0; i < 64; i++) nz |= ei[2 * i + 1];
        g_ei32 = (nz != 0) ? 1 : 0;
    }
}

// ---------------- fused GEMM ----------------
// C[128-row tile x 64] = act(A[. x KDIM]) @ W[KDIM x 64]
// ACT: 0 identity, 1 relu, 2 BN-affine(from banked sums)+relu
// EPI: 0 write Y=C and AGG=(1+eps)*C+bias ; 1 U=relu(C+bias)->Y + banked BN sums
// 128 threads, 8 rows x 8 cols per thread: 16 smem floats per 64 FMAs
// (1.0 B/FMA vs 1.5 before) — targets the measured smem-crossbar bound.
// r0=(tid>>3)*8 (8-way A broadcast), c0=(tid&7)*8 (4-way W broadcast).
// Dynamic smem: [ w_sh KDIM*64 | a_sh 64*ASTR ]; ASTR=136 (544B=34*16B).
template<int KDIM, int ACT, int EPI>
__global__ __launch_bounds__(128) void gemm_kernel(
    const float* __restrict__ A, const float* __restrict__ W,
    const float* __restrict__ bias, const float* __restrict__ epsp,
    const float* __restrict__ bng, const float* __restrict__ bnb,
    float* __restrict__ Y, float* __restrict__ AGG)
{
    constexpr int ASTR = 136;

    extern __shared__ __align__(16) float smem_dyn[];
    float* w_sh = smem_dyn;                 // KDIM*64 floats
    float* a_sh = smem_dyn + KDIM * 64;     // 64*ASTR floats

    __shared__ float bnsc[64];
    __shared__ float bnsh[64];
    __shared__ float bsum[64];
    __shared__ float bsq[64];

    const int tid = threadIdx.x;

    for (int i = tid; i < KDIM * 64; i += 128) w_sh[i] = W[i];
    if (ACT == 2 && tid < 64) {
        double s = 0.0, q = 0.0;
#pragma unroll
        for (int b = 0; b < NBANK; b++) { s += g_sumB[b][tid]; q += g_sqB[b][tid]; }
        double m = s / (double)NN;
        double v = q / (double)NN - m * m;
        float sc = bng[tid] * rsqrtf((float)v + 1e-5f);
        bnsc[tid] = sc;
        bnsh[tid] = bnb[tid] - (float)m * sc;
    }
    if (EPI == 1 && tid < 64) { bsum[tid] = 0.f; bsq[tid] = 0.f; }
    __syncthreads();

    const int row0 = blockIdx.x * 128;
    const int r0 = (tid >> 3) * 8;       // 0..120
    const int c0 = (tid & 7) * 8;        // 0..56

    float acc[8][8];
#pragma unroll
    for (int i = 0; i < 8; i++)
#pragma unroll
        for (int j = 0; j < 8; j++) acc[i][j] = 0.f;

    for (int k0 = 0; k0 < KDIM; k0 += 64) {
        if (k0 > 0) __syncthreads();
        // stage A chunk transposed+activated: 128 rows x 64 cols
#pragma unroll
        for (int it = 0; it < 16; it++) {
            int idx = tid + it * 128;    // 0..2047
            int row = idx >> 4;          // 0..127
            int c4 = idx & 15;           // 0..15
            int grow = row0 + row;
            float4 v = make_float4(0.f, 0.f, 0.f, 0.f);
            if (grow < NN)
                v = *(const float4*)(A + (size_t)grow * KDIM + k0 + c4 * 4);
            if (ACT == 1) {
                v.x = fmaxf(v.x, 0.f); v.y = fmaxf(v.y, 0.f);
                v.z = fmaxf(v.z, 0.f); v.w = fmaxf(v.w, 0.f);
            } else if (ACT == 2) {
                int kb = k0 + c4 * 4;
                v.x = fmaxf(fmaf(v.x, bnsc[kb + 0], bnsh[kb + 0]), 0.f);
                v.y = fmaxf(fmaf(v.y, bnsc[kb + 1], bnsh[kb + 1]), 0.f);
                v.z = fmaxf(fmaf(v.z, bnsc[kb + 2], bnsh[kb + 2]), 0.f);
                v.w = fmaxf(fmaf(v.w, bnsc[kb + 3], bnsh[kb + 3]), 0.f);
            }
            a_sh[(c4 * 4 + 0) * ASTR + row] = v.x;
            a_sh[(c4 * 4 + 1) * ASTR + row] = v.y;
            a_sh[(c4 * 4 + 2) * ASTR + row] = v.z;
            a_sh[(c4 * 4 + 3) * ASTR + row] = v.w;
        }
        __syncthreads();
#pragma unroll 8
        for (int kk = 0; kk < 64; kk++) {
            float4 a0 = *(const float4*)(a_sh + kk * ASTR + r0);
            float4 a1 = *(const float4*)(a_sh + kk * ASTR + r0 + 4);
            float4 w0 = *(const float4*)(w_sh + (k0 + kk) * 64 + c0);
            float4 w1 = *(const float4*)(w_sh + (k0 + kk) * 64 + c0 + 4);
            float av[8] = {a0.x, a0.y, a0.z, a0.w, a1.x, a1.y, a1.z, a1.w};
            float wl[8] = {w0.x, w0.y, w0.z, w0.w, w1.x, w1.y, w1.z, w1.w};
#pragma unroll
            for (int i = 0; i < 8; i++)
#pragma unroll
                for (int j = 0; j < 8; j++)
                    acc[i][j] = fmaf(av[i], wl[j], acc[i][j]);
        }
    }

    if (EPI == 0) {
        float ep = 1.0f + *epsp;
        float4 b0 = *(const float4*)(bias + c0);
        float4 b1 = *(const float4*)(bias + c0 + 4);
        float bb[8] = {b0.x, b0.y, b0.z, b0.w, b1.x, b1.y, b1.z, b1.w};
#pragma unroll
        for (int i = 0; i < 8; i++) {
            int grow = row0 + r0 + i;
            if (grow < NN) {
                float* yrow = Y + (size_t)grow * 64 + c0;
                float* arow = AGG + (size_t)grow * 64 + c0;
                *(float4*)(yrow)     = make_float4(acc[i][0], acc[i][1], acc[i][2], acc[i][3]);
                *(float4*)(yrow + 4) = make_float4(acc[i][4], acc[i][5], acc[i][6], acc[i][7]);
                *(float4*)(arow)     = make_float4(fmaf(acc[i][0], ep, bb[0]), fmaf(acc[i][1], ep, bb[1]),
                                                   fmaf(acc[i][2], ep, bb[2]), fmaf(acc[i][3], ep, bb[3]));
                *(float4*)(arow + 4) = make_float4(fmaf(acc[i][4], ep, bb[4]), fmaf(acc[i][5], ep, bb[5]),
                                                   fmaf(acc[i][6], ep, bb[6]), fmaf(acc[i][7], ep, bb[7]));
            }
        }
    } else {
        float4 b0 = *(const float4*)(bias + c0);
        float4 b1 = *(const float4*)(bias + c0 + 4);
        float bb[8] = {b0.x, b0.y, b0.z, b0.w, b1.x, b1.y, b1.z, b1.w};
        float ps[8], pq[8];
#pragma unroll
        for (int j = 0; j < 8; j++) { ps[j] = 0.f; pq[j] = 0.f; }
#pragma unroll
        for (int i = 0; i < 8; i++) {
            int grow = row0 + r0 + i;
            if (grow < NN) {
                float u[8];
#pragma unroll
                for (int j = 0; j < 8; j++) {
                    u[j] = fmaxf(acc[i][j] + bb[j], 0.f);
                    ps[j] += u[j];
                    pq[j] += u[j] * u[j];
                }
                float* yrow = Y + (size_t)grow * 64 + c0;
                *(float4*)(yrow)     = make_float4(u[0], u[1], u[2], u[3]);
                *(float4*)(yrow + 4) = make_float4(u[4], u[5], u[6], u[7]);
            }
        }
#pragma unroll
        for (int j = 0; j < 8; j++) {
            atomicAdd(&bsum[c0 + j], ps[j]);
            atomicAdd(&bsq[c0 + j], pq[j]);
        }
        __syncthreads();
        if (tid < 64) {
            int bank = blockIdx.x & (NBANK - 1);
            atomicAdd(&g_sumB[bank][tid], (double)bsum[tid]);
            atomicAdd(&g_sqB[bank][tid], (double)bsq[tid]);
        }
    }
}

// ---------------- scatter-add over edges ----------------
// agg[dst] += y[src]; 16 threads/edge, one float4 red each.
// Block 0 resets banked BN accumulators (sits between consumer and producer).
__global__ __launch_bounds__(256) void scatter_kernel(const void* __restrict__ eiv)
{
    if (blockIdx.x == 0) {
        for (int i = threadIdx.x; i < NBANK * HH; i += 256) {
            ((double*)g_sumB)[i] = 0.0;
            ((double*)g_sqB)[i] = 0.0;
        }
    }
    int t = blockIdx.x * 256 + threadIdx.x;
    int e = t >> 4;
    int c = t & 15;
    if (e >= EE) return;
    int s, d;
    if (g_ei32) {
        const int* ei = (const int*)eiv;
        s = __ldg(ei + e);
        d = __ldg(ei + EE + e);
    } else {
        const long long* ei = (const long long*)eiv;
        s = (int)__ldg(ei + e);
        d = (int)__ldg(ei + EE + e);
    }
    float4 v = __ldg(((const float4*)g_y) + (size_t)s * 16 + c);
    float* p = g_agg + ((size_t)d * 64 + c * 4);
    asm volatile("red.global.add.v4.f32 [%0], {%1,%2,%3,%4};"
                 :: "l"(p), "f"(v.x), "f"(v.y), "f"(v.z), "f"(v.w)
                 : "memory");
}

// ---------------- final: out = bn_relu(u3) @ lin_w + lin_b ----------------
__global__ __launch_bounds__(128) void final_kernel(
    const float* __restrict__ bng, const float* __restrict__ bnb,
    const float* __restrict__ lw, const float* __restrict__ lb,
    float* __restrict__ out)
{
    __shared__ float a_sh[128 * 65];
    __shared__ float w_sh[64 * 10];
    __shared__ float b_sh[10];
    __shared__ float bnsc[64];
    __shared__ float bnsh[64];

    int tid = threadIdx.x;
    if (tid < 64) {
        double s = 0.0, q = 0.0;
#pragma unroll
        for (int b = 0; b < NBANK; b++) { s += g_sumB[b][tid]; q += g_sqB[b][tid]; }
        double m = s / (double)NN;
        double v = q / (double)NN - m * m;
        float sc = bng[tid] * rsqrtf((float)v + 1e-5f);
        bnsc[tid] = sc;
        bnsh[tid] = bnb[tid] - (float)m * sc;
    }
    for (int i = tid; i < 640; i += 128) w_sh[i] = lw[i];
    if (tid < 10) b_sh[tid] = lb[tid];
    __syncthreads();

    int row0 = blockIdx.x * 128;
    for (int idx = tid; idx < 128 * 64; idx += 128) {
        int r = idx >> 6;
        int k = idx & 63;
        int grow = row0 + r;
        float val = 0.f;
        if (grow < NN) val = g_u[(size_t)grow * 64 + k];
        a_sh[r * 65 + k] = fmaxf(fmaf(val, bnsc[k], bnsh[k]), 0.f);
    }
    __syncthreads();

    int grow = row0 + tid;
    if (grow < NN) {
        float a[64];
#pragma unroll
        for (int k = 0; k < 64; k++) a[k] = a_sh[tid * 65 + k];
        float accv[10];
#pragma unroll
        for (int c = 0; c < 10; c++) accv[c] = b_sh[c];
#pragma unroll
        for (int k = 0; k < 64; k++)
#pragma unroll
            for (int c = 0; c < 10; c++)
                accv[c] = fmaf(a[k], w_sh[k * 10 + c], accv[c]);
#pragma unroll
        for (int c = 0; c < 10; c++) out[(size_t)grow * 10 + c] = accv[c];
    }
}

// ---------------- launch ----------------
extern "C" void kernel_launch(void* const* d_in, const int* in_sizes, int n_in,
                              void* d_out, int out_size)
{
    const float* x       = (const float*)d_in[0];
    const void*  ei      = d_in[1];
    const float* eps1    = (const float*)d_in[2];
    const float* w1a     = (const float*)d_in[3];
    const float* b1a     = (const float*)d_in[4];
    const float* w1b     = (const float*)d_in[5];
    const float* b1b     = (const float*)d_in[6];
    const float* g1      = (const float*)d_in[7];
    const float* be1     = (const float*)d_in[8];
    const float* eps2    = (const float*)d_in[9];
    const float* w2a     = (const float*)d_in[10];
    const float* b2a     = (const float*)d_in[11];
    const float* w2b     = (const float*)d_in[12];
    const float* b2b     = (const float*)d_in[13];
    const float* g2      = (const float*)d_in[14];
    const float* be2     = (const float*)d_in[15];
    const float* eps3    = (const float*)d_in[16];
    const float* w3a     = (const float*)d_in[17];
    const float* b3a     = (const float*)d_in[18];
    const float* w3b     = (const float*)d_in[19];
    const float* b3b     = (const float*)d_in[20];
    const float* g3      = (const float*)d_in[21];
    const float* be3     = (const float*)d_in[22];
    const float* lin_w   = (const float*)d_in[23];
    const float* lin_b   = (const float*)d_in[24];
    float* out = (float*)d_out;

    float *yp = nullptr, *ap = nullptr, *up = nullptr;
    cudaGetSymbolAddress((void**)&yp, g_y);
    cudaGetSymbolAddress((void**)&ap, g_agg);
    cudaGetSymbolAddress((void**)&up, g_u);

    const int gemm_blocks = (NN + 127) / 128;          // 391
    const int scat_blocks = (EE * 16) / 256;           // 50000

    constexpr int ASTR = 136;
    const int smem64  = (64 * 64 + 64 * ASTR) * 4;     // 51200 B
    const int smem128 = (128 * 64 + 64 * ASTR) * 4;    // 67584 B

    static int attr_done = 0;
    if (!attr_done) {
        cudaFuncSetAttribute(gemm_kernel<128, 0, 0>,
                             cudaFuncAttributeMaxDynamicSharedMemorySize, smem128);
        cudaFuncSetAttribute(gemm_kernel<64, 1, 1>,
                             cudaFuncAttributeMaxDynamicSharedMemorySize, smem64);
        cudaFuncSetAttribute(gemm_kernel<64, 2, 0>,
                             cudaFuncAttributeMaxDynamicSharedMemorySize, smem64);
        attr_done = 1;
    }

    detect_dtype_kernel<<<1, 32>>>((const int*)ei);

    // ---- layer 1 ----
    gemm_kernel<128, 0, 0><<<gemm_blocks, 128, smem128>>>(x, w1a, b1a, eps1, nullptr, nullptr, yp, ap);
    scatter_kernel<<<scat_blocks, 256>>>(ei);
    gemm_kernel<64, 1, 1><<<gemm_blocks, 128, smem64>>>(ap, w1b, b1b, nullptr, nullptr, nullptr, up, nullptr);

    // ---- layer 2 ----
    gemm_kernel<64, 2, 0><<<gemm_blocks, 128, smem64>>>(up, w2a, b2a, eps2, g1, be1, yp, ap);
    scatter_kernel<<<scat_blocks, 256>>>(ei);
    gemm_kernel<64, 1, 1><<<gemm_blocks, 128, smem64>>>(ap, w2b, b2b, nullptr, nullptr, nullptr, up, nullptr);

    // ---- layer 3 ----
    gemm_kernel<64, 2, 0><<<gemm_blocks, 128, smem64>>>(up, w3a, b3a, eps3, g2, be2, yp, ap);
    scatter_kernel<<<scat_blocks, 256>>>(ei);
    gemm_kernel<64, 1, 1><<<gemm_blocks, 128, smem64>>>(ap, w3b, b3b, nullptr, nullptr, nullptr, up, nullptr);

    // ---- classifier ----
    final_kernel<<<(NN + 127) / 128, 128>>>(g3, be3, lin_w, lin_b, out);
}

// round 15
// speedup vs baseline: 1.4396x; 1.4396x over previous
#include <cuda_runtime.h>
#include <cuda_bf16.h>
#include <cstdint>

#define NN 50000
#define EE 800000
#define HH 64
#define NBANK 8

// ---------------- device scratch (no allocation allowed) ----------------
__device__ __align__(16) float g_y[(size_t)NN * HH];
__device__ __align__(16) float g_agg[(size_t)NN * HH];
__device__ __align__(16) float g_u[(size_t)NN * HH];
__device__ double g_sumB[NBANK][HH];
__device__ double g_sqB[NBANK][HH];
__device__ int g_ei32;

__device__ __forceinline__ uint32_t smem_u32(const void* p) {
    uint32_t a;
    asm("{ .reg .u64 t; cvta.to.shared.u64 t, %1; cvt.u32.u64 %0, t; }" : "=r"(a) : "l"(p));
    return a;
}
__device__ __forceinline__ void ldsm_x4(uint32_t& r0, uint32_t& r1, uint32_t& r2, uint32_t& r3,
                                        uint32_t addr) {
    asm volatile("ldmatrix.sync.aligned.m8n8.x4.shared.b16 {%0,%1,%2,%3}, [%4];"
                 : "=r"(r0), "=r"(r1), "=r"(r2), "=r"(r3) : "r"(addr));
}
__device__ __forceinline__ void ldsm_x2t(uint32_t& r0, uint32_t& r1, uint32_t addr) {
    asm volatile("ldmatrix.sync.aligned.m8n8.x2.trans.shared.b16 {%0,%1}, [%2];"
                 : "=r"(r0), "=r"(r1) : "r"(addr));
}
__device__ __forceinline__ void mma_bf16(float* c, const uint32_t* a, const uint32_t* b) {
    asm volatile(
        "mma.sync.aligned.m16n8k16.row.col.f32.bf16.bf16.f32 "
        "{%0,%1,%2,%3}, {%4,%5,%6,%7}, {%8,%9}, {%0,%1,%2,%3};"
        : "+f"(c[0]), "+f"(c[1]), "+f"(c[2]), "+f"(c[3])
        : "r"(a[0]), "r"(a[1]), "r"(a[2]), "r"(a[3]), "r"(b[0]), "r"(b[1]));
}

// Probe edge_index dtype (int32 vs int64). Deterministic.
__global__ void detect_dtype_kernel(const int* __restrict__ ei) {
    if (threadIdx.x == 0) {
        int nz = 0;
#pragma unroll
        for (int i = 0; i < 64; i++) nz |= ei[2 * i + 1];
        g_ei32 = (nz != 0) ? 1 : 0;
    }
}

// ---------------- HMMA bf16-split fused GEMM ----------------
// C[128 x 64] = act(A[. x KDIM]) @ W[KDIM x 64] via Ahi@Bhi+Ahi@Blo+Alo@Bhi.
// ACT: 0 identity, 1 relu, 2 BN-affine(banked sums)+relu (on A load)
// EPI: 0 Y=C, AGG=(1+eps)*C+bias ; 1 Y=relu(C+bias) + banked BN sums
// 256 threads / 8 warps; warp w owns rows [w*16, w*16+16).
// Smem: Ahi/Alo 128x72 bf16 (pad 72 -> 144B row, conflict-free ldmatrix),
//       Bhi/Blo 64x72 bf16 ([k][n] layout for x2.trans b-frags).
template<int KDIM, int ACT, int EPI>
__global__ __launch_bounds__(256) void tc_gemm(
    const float* __restrict__ A, const float* __restrict__ W,
    const float* __restrict__ bias, const float* __restrict__ epsp,
    const float* __restrict__ bng, const float* __restrict__ bnb,
    float* __restrict__ Y, float* __restrict__ AGG)
{
    constexpr int AS = 72;            // A row stride (bf16)
    constexpr int BS = 72;            // B row stride (bf16)

    extern __shared__ __align__(16) char smem_raw[];
    __nv_bfloat16* sAhi = (__nv_bfloat16*)smem_raw;                 // 128*72
    __nv_bfloat16* sAlo = sAhi + 128 * AS;                          // 128*72
    __nv_bfloat16* sBhi = sAlo + 128 * AS;                          // 64*72
    __nv_bfloat16* sBlo = sBhi + 64 * BS;                           // 64*72

    __shared__ float bnsc[64], bnsh[64], bb[64], bsum[64], bsq[64];

    const int tid = threadIdx.x, wid = tid >> 5, lane = tid & 31;

    if (tid < 64) bb[tid] = bias[tid];
    if (ACT == 2 && tid < 64) {
        double s = 0.0, q = 0.0;
#pragma unroll
        for (int b = 0; b < NBANK; b++) { s += g_sumB[b][tid]; q += g_sqB[b][tid]; }
        double m = s / (double)NN;
        double v = q / (double)NN - m * m;
        float sc = bng[tid] * rsqrtf((float)v + 1e-5f);
        bnsc[tid] = sc;
        bnsh[tid] = bnb[tid] - (float)m * sc;
    }
    if (EPI == 1 && tid < 64) { bsum[tid] = 0.f; bsq[tid] = 0.f; }
    __syncthreads();

    const int row0 = blockIdx.x * 128;
    const int r0 = wid * 16;

    float acc[8][4];
#pragma unroll
    for (int nt = 0; nt < 8; nt++)
#pragma unroll
        for (int j = 0; j < 4; j++) acc[nt][j] = 0.f;

    constexpr int NCH = KDIM / 64;
    for (int ch = 0; ch < NCH; ch++) {
        if (ch > 0) __syncthreads();
        const int k0 = ch * 64;

        // ---- stage A chunk (128 x 64) as bf16 hi/lo ----
#pragma unroll
        for (int it = 0; it < 8; it++) {
            int idx = tid + it * 256;     // 0..2047
            int row = idx >> 4, c4 = idx & 15;
            int grow = row0 + row;
            float4 v = make_float4(0.f, 0.f, 0.f, 0.f);
            if (grow < NN)
                v = *(const float4*)(A + (size_t)grow * KDIM + k0 + c4 * 4);
            if (ACT == 1) {
                v.x = fmaxf(v.x, 0.f); v.y = fmaxf(v.y, 0.f);
                v.z = fmaxf(v.z, 0.f); v.w = fmaxf(v.w, 0.f);
            } else if (ACT == 2) {
                int kb = c4 * 4;
                v.x = fmaxf(fmaf(v.x, bnsc[kb + 0], bnsh[kb + 0]), 0.f);
                v.y = fmaxf(fmaf(v.y, bnsc[kb + 1], bnsh[kb + 1]), 0.f);
                v.z = fmaxf(fmaf(v.z, bnsc[kb + 2], bnsh[kb + 2]), 0.f);
                v.w = fmaxf(fmaf(v.w, bnsc[kb + 3], bnsh[kb + 3]), 0.f);
            }
            float xs[4] = {v.x, v.y, v.z, v.w};
            unsigned short h[4], l[4];
#pragma unroll
            for (int j = 0; j < 4; j++) {
                __nv_bfloat16 hb = __float2bfloat16(xs[j]);
                __nv_bfloat16 lb = __float2bfloat16(xs[j] - __bfloat162float(hb));
                h[j] = __bfloat16_as_ushort(hb);
                l[j] = __bfloat16_as_ushort(lb);
            }
            uint2 hv, lv;
            hv.x = (uint32_t)h[0] | ((uint32_t)h[1] << 16);
            hv.y = (uint32_t)h[2] | ((uint32_t)h[3] << 16);
            lv.x = (uint32_t)l[0] | ((uint32_t)l[1] << 16);
            lv.y = (uint32_t)l[2] | ((uint32_t)l[3] << 16);
            *(uint2*)(sAhi + row * AS + c4 * 4) = hv;
            *(uint2*)(sAlo + row * AS + c4 * 4) = lv;
        }
        // ---- stage B chunk [k][n] (64 x 64) as bf16 hi/lo ----
#pragma unroll
        for (int it = 0; it < 16; it++) {
            int idx = tid + it * 256;     // 0..4095
            int k = idx >> 6, n = idx & 63;
            float w = W[(size_t)(k0 + k) * 64 + n];
            __nv_bfloat16 hb = __float2bfloat16(w);
            __nv_bfloat16 lb = __float2bfloat16(w - __bfloat162float(hb));
            sBhi[k * BS + n] = hb;
            sBlo[k * BS + n] = lb;
        }
        __syncthreads();

        const uint32_t aBaseHi = smem_u32(sAhi);
        const uint32_t aBaseLo = smem_u32(sAlo);
        const uint32_t bBaseHi = smem_u32(sBhi);
        const uint32_t bBaseLo = smem_u32(sBlo);

#pragma unroll
        for (int ks = 0; ks < 4; ks++) {
            const int kk = ks * 16;
            // B fragments for this k-step: 8 n-tiles, hi+lo
            uint32_t bh[8][2], bl[8][2];
            const uint32_t brow = (uint32_t)(kk + (lane & 15)) * BS * 2;
#pragma unroll
            for (int nt = 0; nt < 8; nt++) {
                ldsm_x2t(bh[nt][0], bh[nt][1], bBaseHi + brow + nt * 16);
                ldsm_x2t(bl[nt][0], bl[nt][1], bBaseLo + brow + nt * 16);
            }
            // A fragments hi/lo
            uint32_t ah[4], al[4];
            const uint32_t aoff = (uint32_t)((r0 + (lane & 15)) * AS + kk + (lane >> 4) * 8) * 2;
            ldsm_x4(ah[0], ah[1], ah[2], ah[3], aBaseHi + aoff);
            ldsm_x4(al[0], al[1], al[2], al[3], aBaseLo + aoff);
#pragma unroll
            for (int nt = 0; nt < 8; nt++) {
                mma_bf16(acc[nt], ah, bh[nt]);
                mma_bf16(acc[nt], ah, bl[nt]);
                mma_bf16(acc[nt], al, bh[nt]);
            }
        }
    }

    // ---- epilogue: c-frag mapping rows r0+lane/4 (+8), cols nt*8+(lane%4)*2 ----
    const int rA = row0 + r0 + (lane >> 2);
    const int rB = rA + 8;
    const int cb = (lane & 3) * 2;

    if (EPI == 0) {
        float ep = 1.0f + *epsp;
#pragma unroll
        for (int half = 0; half < 2; half++) {
            int grow = half ? rB : rA;
            if (grow < NN) {
                float* yr = Y + (size_t)grow * 64;
                float* ar = AGG + (size_t)grow * 64;
#pragma unroll
                for (int nt = 0; nt < 8; nt++) {
                    float v0 = acc[nt][half * 2 + 0];
                    float v1 = acc[nt][half * 2 + 1];
                    int c = nt * 8 + cb;
                    *(float2*)(yr + c) = make_float2(v0, v1);
                    *(float2*)(ar + c) = make_float2(fmaf(v0, ep, bb[c]), fmaf(v1, ep, bb[c + 1]));
                }
            }
        }
    } else {
        float ps[8][2], pq[8][2];
#pragma unroll
        for (int nt = 0; nt < 8; nt++) {
            ps[nt][0] = ps[nt][1] = 0.f;
            pq[nt][0] = pq[nt][1] = 0.f;
        }
#pragma unroll
        for (int half = 0; half < 2; half++) {
            int grow = half ? rB : rA;
            bool valid = (grow < NN);
            float* yr = Y + (size_t)grow * 64;
#pragma unroll
            for (int nt = 0; nt < 8; nt++) {
                int c = nt * 8 + cb;
                float u0 = 0.f, u1 = 0.f;
                if (valid) {
                    u0 = fmaxf(acc[nt][half * 2 + 0] + bb[c], 0.f);
                    u1 = fmaxf(acc[nt][half * 2 + 1] + bb[c + 1], 0.f);
                    *(float2*)(yr + c) = make_float2(u0, u1);
                }
                ps[nt][0] += u0; ps[nt][1] += u1;
                pq[nt][0] += u0 * u0; pq[nt][1] += u1 * u1;
            }
        }
        // reduce over rows: lanes differing in bits 2,3,4 share columns
#pragma unroll
        for (int nt = 0; nt < 8; nt++) {
#pragma unroll
            for (int q = 0; q < 2; q++) {
#pragma unroll
                for (int o = 4; o <= 16; o <<= 1) {
                    ps[nt][q] += __shfl_xor_sync(0xffffffffu, ps[nt][q], o);
                    pq[nt][q] += __shfl_xor_sync(0xffffffffu, pq[nt][q], o);
                }
            }
        }
        if (lane < 4) {
#pragma unroll
            for (int nt = 0; nt < 8; nt++) {
                int c = nt * 8 + lane * 2;
                atomicAdd(&bsum[c], ps[nt][0]);
                atomicAdd(&bsum[c + 1], ps[nt][1]);
                atomicAdd(&bsq[c], pq[nt][0]);
                atomicAdd(&bsq[c + 1], pq[nt][1]);
            }
        }
        __syncthreads();
        if (tid < 64) {
            int bank = blockIdx.x & (NBANK - 1);
            atomicAdd(&g_sumB[bank][tid], (double)bsum[tid]);
            atomicAdd(&g_sqB[bank][tid], (double)bsq[tid]);
        }
    }
}

// ---------------- scatter-add over edges ----------------
__global__ __launch_bounds__(256) void scatter_kernel(const void* __restrict__ eiv)
{
    if (blockIdx.x == 0) {
        for (int i = threadIdx.x; i < NBANK * HH; i += 256) {
            ((double*)g_sumB)[i] = 0.0;
            ((double*)g_sqB)[i] = 0.0;
        }
    }
    int t = blockIdx.x * 256 + threadIdx.x;
    int e = t >> 4;
    int c = t & 15;
    if (e >= EE) return;
    int s, d;
    if (g_ei32) {
        const int* ei = (const int*)eiv;
        s = __ldg(ei + e);
        d = __ldg(ei + EE + e);
    } else {
        const long long* ei = (const long long*)eiv;
        s = (int)__ldg(ei + e);
        d = (int)__ldg(ei + EE + e);
    }
    float4 v = __ldg(((const float4*)g_y) + (size_t)s * 16 + c);
    float* p = g_agg + ((size_t)d * 64 + c * 4);
    asm volatile("red.global.add.v4.f32 [%0], {%1,%2,%3,%4};"
                 :: "l"(p), "f"(v.x), "f"(v.y), "f"(v.z), "f"(v.w)
                 : "memory");
}

// ---------------- final: out = bn_relu(u3) @ lin_w + lin_b ----------------
__global__ __launch_bounds__(128) void final_kernel(
    const float* __restrict__ bng, const float* __restrict__ bnb,
    const float* __restrict__ lw, const float* __restrict__ lb,
    float* __restrict__ out)
{
    __shared__ float a_sh[128 * 65];
    __shared__ float w_sh[64 * 10];
    __shared__ float b_sh[10];
    __shared__ float bnsc[64];
    __shared__ float bnsh[64];

    int tid = threadIdx.x;
    if (tid < 64) {
        double s = 0.0, q = 0.0;
#pragma unroll
        for (int b = 0; b < NBANK; b++) { s += g_sumB[b][tid]; q += g_sqB[b][tid]; }
        double m = s / (double)NN;
        double v = q / (double)NN - m * m;
        float sc = bng[tid] * rsqrtf((float)v + 1e-5f);
        bnsc[tid] = sc;
        bnsh[tid] = bnb[tid] - (float)m * sc;
    }
    for (int i = tid; i < 640; i += 128) w_sh[i] = lw[i];
    if (tid < 10) b_sh[tid] = lb[tid];
    __syncthreads();

    int row0 = blockIdx.x * 128;
    for (int idx = tid; idx < 128 * 64; idx += 128) {
        int r = idx >> 6;
        int k = idx & 63;
        int grow = row0 + r;
        float val = 0.f;
        if (grow < NN) val = g_u[(size_t)grow * 64 + k];
        a_sh[r * 65 + k] = fmaxf(fmaf(val, bnsc[k], bnsh[k]), 0.f);
    }
    __syncthreads();

    int grow = row0 + tid;
    if (grow < NN) {
        float a[64];
#pragma unroll
        for (int k = 0; k < 64; k++) a[k] = a_sh[tid * 65 + k];
        float accv[10];
#pragma unroll
        for (int c = 0; c < 10; c++) accv[c] = b_sh[c];
#pragma unroll
        for (int k = 0; k < 64; k++)
#pragma unroll
            for (int c = 0; c < 10; c++)
                accv[c] = fmaf(a[k], w_sh[k * 10 + c], accv[c]);
#pragma unroll
        for (int c = 0; c < 10; c++) out[(size_t)grow * 10 + c] = accv[c];
    }
}

// ---------------- launch ----------------
extern "C" void kernel_launch(void* const* d_in, const int* in_sizes, int n_in,
                              void* d_out, int out_size)
{
    const float* x       = (const float*)d_in[0];
    const void*  ei      = d_in[1];
    const float* eps1    = (const float*)d_in[2];
    const float* w1a     = (const float*)d_in[3];
    const float* b1a     = (const float*)d_in[4];
    const float* w1b     = (const float*)d_in[5];
    const float* b1b     = (const float*)d_in[6];
    const float* g1      = (const float*)d_in[7];
    const float* be1     = (const float*)d_in[8];
    const float* eps2    = (const float*)d_in[9];
    const float* w2a     = (const float*)d_in[10];
    const float* b2a     = (const float*)d_in[11];
    const float* w2b     = (const float*)d_in[12];
    const float* b2b     = (const float*)d_in[13];
    const float* g2      = (const float*)d_in[14];
    const float* be2     = (const float*)d_in[15];
    const float* eps3    = (const float*)d_in[16];
    const float* w3a     = (const float*)d_in[17];
    const float* b3a     = (const float*)d_in[18];
    const float* w3b     = (const float*)d_in[19];
    const float* b3b     = (const float*)d_in[20];
    const float* g3      = (const float*)d_in[21];
    const float* be3     = (const float*)d_in[22];
    const float* lin_w   = (const float*)d_in[23];
    const float* lin_b   = (const float*)d_in[24];
    float* out = (float*)d_out;

    float *yp = nullptr, *ap = nullptr, *up = nullptr;
    cudaGetSymbolAddress((void**)&yp, g_y);
    cudaGetSymbolAddress((void**)&ap, g_agg);
    cudaGetSymbolAddress((void**)&up, g_u);

    const int gemm_blocks = (NN + 127) / 128;          // 391
    const int scat_blocks = (EE * 16) / 256;           // 50000
    // smem: A 2*128*72*2 + B 2*64*72*2 = 36864 + 18432 = 55296 B
    const int smem_bytes = 2 * 128 * 72 * 2 + 2 * 64 * 72 * 2;

    static int attr_done = 0;
    if (!attr_done) {
        cudaFuncSetAttribute(tc_gemm<128, 0, 0>,
                             cudaFuncAttributeMaxDynamicSharedMemorySize, smem_bytes);
        cudaFuncSetAttribute(tc_gemm<64, 1, 1>,
                             cudaFuncAttributeMaxDynamicSharedMemorySize, smem_bytes);
        cudaFuncSetAttribute(tc_gemm<64, 2, 0>,
                             cudaFuncAttributeMaxDynamicSharedMemorySize, smem_bytes);
        attr_done = 1;
    }

    detect_dtype_kernel<<<1, 32>>>((const int*)ei);

    // ---- layer 1 ----
    tc_gemm<128, 0, 0><<<gemm_blocks, 256, smem_bytes>>>(x, w1a, b1a, eps1, nullptr, nullptr, yp, ap);
    scatter_kernel<<<scat_blocks, 256>>>(ei);
    tc_gemm<64, 1, 1><<<gemm_blocks, 256, smem_bytes>>>(ap, w1b, b1b, nullptr, nullptr, nullptr, up, nullptr);

    // ---- layer 2 ----
    tc_gemm<64, 2, 0><<<gemm_blocks, 256, smem_bytes>>>(up, w2a, b2a, eps2, g1, be1, yp, ap);
    scatter_kernel<<<scat_blocks, 256>>>(ei);
    tc_gemm<64, 1, 1><<<gemm_blocks, 256, smem_bytes>>>(ap, w2b, b2b, nullptr, nullptr, nullptr, up, nullptr);

    // ---- layer 3 ----
    tc_gemm<64, 2, 0><<<gemm_blocks, 256, smem_bytes>>>(up, w3a, b3a, eps3, g2, be2, yp, ap);
    scatter_kernel<<<scat_blocks, 256>>>(ei);
    tc_gemm<64, 1, 1><<<gemm_blocks, 256, smem_bytes>>>(ap, w3b, b3b, nullptr, nullptr, nullptr, up, nullptr);

    // ---- classifier ----
    final_kernel<<<(NN + 127) / 128, 128>>>(g3, be3, lin_w, lin_b, out);
}

// round 16
// speedup vs baseline: 1.4674x; 1.0193x over previous
#include <cuda_runtime.h>
#include <cuda_bf16.h>
#include <cstdint>

#define NN 50000
#define EE 800000
#define HH 64
#define NBANK 8
#define WTOT 28672

// ---------------- device scratch (no allocation allowed) ----------------
__device__ __align__(16) float g_y[(size_t)NN * HH];
__device__ __align__(16) float g_agg[(size_t)NN * HH];
__device__ __align__(16) float g_u[(size_t)NN * HH];
__device__ __align__(16) __nv_bfloat16 g_whi[WTOT];   // pre-split weights hi
__device__ __align__(16) __nv_bfloat16 g_wlo[WTOT];   // pre-split weights lo
__device__ double g_sumB[NBANK][HH];
__device__ double g_sqB[NBANK][HH];
__device__ int g_ei32;

__device__ __forceinline__ uint32_t smem_u32(const void* p) {
    uint32_t a;
    asm("{ .reg .u64 t; cvta.to.shared.u64 t, %1; cvt.u32.u64 %0, t; }" : "=r"(a) : "l"(p));
    return a;
}
__device__ __forceinline__ void ldsm_x4(uint32_t& r0, uint32_t& r1, uint32_t& r2, uint32_t& r3,
                                        uint32_t addr) {
    asm volatile("ldmatrix.sync.aligned.m8n8.x4.shared.b16 {%0,%1,%2,%3}, [%4];"
                 : "=r"(r0), "=r"(r1), "=r"(r2), "=r"(r3) : "r"(addr));
}
__device__ __forceinline__ void ldsm_x2t(uint32_t& r0, uint32_t& r1, uint32_t addr) {
    asm volatile("ldmatrix.sync.aligned.m8n8.x2.trans.shared.b16 {%0,%1}, [%2];"
                 : "=r"(r0), "=r"(r1) : "r"(addr));
}
__device__ __forceinline__ void mma_bf16(float* c, const uint32_t* a, const uint32_t* b) {
    asm volatile(
        "mma.sync.aligned.m16n8k16.row.col.f32.bf16.bf16.f32 "
        "{%0,%1,%2,%3}, {%4,%5,%6,%7}, {%8,%9}, {%0,%1,%2,%3};"
        : "+f"(c[0]), "+f"(c[1]), "+f"(c[2]), "+f"(c[3])
        : "r"(a[0]), "r"(a[1]), "r"(a[2]), "r"(a[3]), "r"(b[0]), "r"(b[1]));
}

// Probe edge_index dtype (int32 vs int64). Deterministic.
__global__ void detect_dtype_kernel(const int* __restrict__ ei) {
    if (threadIdx.x == 0) {
        int nz = 0;
#pragma unroll
        for (int i = 0; i < 64; i++) nz |= ei[2 * i + 1];
        g_ei32 = (nz != 0) ? 1 : 0;
    }
}

// ---------------- one-time weight split (bf16 hi/lo) ----------------
// Layout in g_whi/g_wlo ([k][n] per matrix):
//   w1a [0, 8192)  w1b [8192, 12288)  w2a [12288, 16384)
//   w2b [16384, 20480)  w3a [20480, 24576)  w3b [24576, 28672)
__global__ void split_w_kernel(const float* __restrict__ w1a, const float* __restrict__ w1b,
                               const float* __restrict__ w2a, const float* __restrict__ w2b,
                               const float* __restrict__ w3a, const float* __restrict__ w3b)
{
    int i = blockIdx.x * 256 + threadIdx.x;
    if (i >= WTOT) return;
    const float* src;
    int off;
    if (i < 8192)       { src = w1a; off = i; }
    else if (i < 12288) { src = w1b; off = i - 8192; }
    else if (i < 16384) { src = w2a; off = i - 12288; }
    else if (i < 20480) { src = w2b; off = i - 16384; }
    else if (i < 24576) { src = w3a; off = i - 20480; }
    else                { src = w3b; off = i - 24576; }
    float w = src[off];
    __nv_bfloat16 hb = __float2bfloat16(w);
    __nv_bfloat16 lb = __float2bfloat16(w - __bfloat162float(hb));
    g_whi[i] = hb;
    g_wlo[i] = lb;
}

// ---------------- HMMA bf16-split fused GEMM ----------------
// C[128 x 64] = act(A[. x KDIM]) @ W[KDIM x 64] via Ahi@Bhi+Ahi@Blo+Alo@Bhi.
// W comes pre-split from g_whi/g_wlo at offset WOFF ([k][n], 64 cols).
// ACT: 0 identity, 1 relu, 2 BN-affine(banked sums)+relu (on A load)
// EPI: 0 Y=C, AGG=(1+eps)*C+bias ; 1 Y=relu(C+bias) + banked BN sums
template<int KDIM, int ACT, int EPI>
__global__ __launch_bounds__(256) void tc_gemm(
    const float* __restrict__ A, int woff,
    const float* __restrict__ bias, const float* __restrict__ epsp,
    const float* __restrict__ bng, const float* __restrict__ bnb,
    float* __restrict__ Y, float* __restrict__ AGG)
{
    constexpr int AS = 72;            // A row stride (bf16)
    constexpr int BS = 72;            // B row stride (bf16)

    extern __shared__ __align__(16) char smem_raw[];
    __nv_bfloat16* sAhi = (__nv_bfloat16*)smem_raw;                 // 128*72
    __nv_bfloat16* sAlo = sAhi + 128 * AS;                          // 128*72
    __nv_bfloat16* sBhi = sAlo + 128 * AS;                          // 64*72
    __nv_bfloat16* sBlo = sBhi + 64 * BS;                           // 64*72

    __shared__ float bnsc[64], bnsh[64], bb[64], bsum[64], bsq[64];

    const int tid = threadIdx.x, wid = tid >> 5, lane = tid & 31;

    if (tid < 64) bb[tid] = bias[tid];
    if (ACT == 2 && tid < 64) {
        double s = 0.0, q = 0.0;
#pragma unroll
        for (int b = 0; b < NBANK; b++) { s += g_sumB[b][tid]; q += g_sqB[b][tid]; }
        double m = s / (double)NN;
        double v = q / (double)NN - m * m;
        float sc = bng[tid] * rsqrtf((float)v + 1e-5f);
        bnsc[tid] = sc;
        bnsh[tid] = bnb[tid] - (float)m * sc;
    }
    if (EPI == 1 && tid < 64) { bsum[tid] = 0.f; bsq[tid] = 0.f; }
    __syncthreads();

    const int row0 = blockIdx.x * 128;
    const int r0 = wid * 16;

    float acc[8][4];
#pragma unroll
    for (int nt = 0; nt < 8; nt++)
#pragma unroll
        for (int j = 0; j < 4; j++) acc[nt][j] = 0.f;

    constexpr int NCH = KDIM / 64;
    for (int ch = 0; ch < NCH; ch++) {
        if (ch > 0) __syncthreads();
        const int k0 = ch * 64;

        // ---- stage A chunk (128 x 64) as bf16 hi/lo ----
#pragma unroll
        for (int it = 0; it < 8; it++) {
            int idx = tid + it * 256;     // 0..2047
            int row = idx >> 4, c4 = idx & 15;
            int grow = row0 + row;
            float4 v = make_float4(0.f, 0.f, 0.f, 0.f);
            if (grow < NN)
                v = *(const float4*)(A + (size_t)grow * KDIM + k0 + c4 * 4);
            if (ACT == 1) {
                v.x = fmaxf(v.x, 0.f); v.y = fmaxf(v.y, 0.f);
                v.z = fmaxf(v.z, 0.f); v.w = fmaxf(v.w, 0.f);
            } else if (ACT == 2) {
                int kb = c4 * 4;
                v.x = fmaxf(fmaf(v.x, bnsc[kb + 0], bnsh[kb + 0]), 0.f);
                v.y = fmaxf(fmaf(v.y, bnsc[kb + 1], bnsh[kb + 1]), 0.f);
                v.z = fmaxf(fmaf(v.z, bnsc[kb + 2], bnsh[kb + 2]), 0.f);
                v.w = fmaxf(fmaf(v.w, bnsc[kb + 3], bnsh[kb + 3]), 0.f);
            }
            float xs[4] = {v.x, v.y, v.z, v.w};
            unsigned short h[4], l[4];
#pragma unroll
            for (int j = 0; j < 4; j++) {
                __nv_bfloat16 hb = __float2bfloat16(xs[j]);
                __nv_bfloat16 lb = __float2bfloat16(xs[j] - __bfloat162float(hb));
                h[j] = __bfloat16_as_ushort(hb);
                l[j] = __bfloat16_as_ushort(lb);
            }
            uint2 hv, lv;
            hv.x = (uint32_t)h[0] | ((uint32_t)h[1] << 16);
            hv.y = (uint32_t)h[2] | ((uint32_t)h[3] << 16);
            lv.x = (uint32_t)l[0] | ((uint32_t)l[1] << 16);
            lv.y = (uint32_t)l[2] | ((uint32_t)l[3] << 16);
            *(uint2*)(sAhi + row * AS + c4 * 4) = hv;
            *(uint2*)(sAlo + row * AS + c4 * 4) = lv;
        }
        // ---- stage B chunk from pre-split weights: pure uint4 copies ----
#pragma unroll
        for (int it = 0; it < 2; it++) {
            int idx = tid + it * 256;     // 0..511
            int k = idx >> 3, n8 = idx & 7;
            *(uint4*)(sBhi + k * BS + n8 * 8) =
                *(const uint4*)(g_whi + woff + (size_t)(k0 + k) * 64 + n8 * 8);
            *(uint4*)(sBlo + k * BS + n8 * 8) =
                *(const uint4*)(g_wlo + woff + (size_t)(k0 + k) * 64 + n8 * 8);
        }
        __syncthreads();

        const uint32_t aBaseHi = smem_u32(sAhi);
        const uint32_t aBaseLo = smem_u32(sAlo);
        const uint32_t bBaseHi = smem_u32(sBhi);
        const uint32_t bBaseLo = smem_u32(sBlo);

#pragma unroll
        for (int ks = 0; ks < 4; ks++) {
            const int kk = ks * 16;
            uint32_t bh[8][2], bl[8][2];
            const uint32_t brow = (uint32_t)(kk + (lane & 15)) * BS * 2;
#pragma unroll
            for (int nt = 0; nt < 8; nt++) {
                ldsm_x2t(bh[nt][0], bh[nt][1], bBaseHi + brow + nt * 16);
                ldsm_x2t(bl[nt][0], bl[nt][1], bBaseLo + brow + nt * 16);
            }
            uint32_t ah[4], al[4];
            const uint32_t aoff = (uint32_t)((r0 + (lane & 15)) * AS + kk + (lane >> 4) * 8) * 2;
            ldsm_x4(ah[0], ah[1], ah[2], ah[3], aBaseHi + aoff);
            ldsm_x4(al[0], al[1], al[2], al[3], aBaseLo + aoff);
#pragma unroll
            for (int nt = 0; nt < 8; nt++) {
                mma_bf16(acc[nt], ah, bh[nt]);
                mma_bf16(acc[nt], ah, bl[nt]);
                mma_bf16(acc[nt], al, bh[nt]);
            }
        }
    }

    // ---- epilogue: c-frag rows r0+lane/4 (+8), cols nt*8+(lane%4)*2 ----
    const int rA = row0 + r0 + (lane >> 2);
    const int rB = rA + 8;
    const int cb = (lane & 3) * 2;

    if (EPI == 0) {
        float ep = 1.0f + *epsp;
#pragma unroll
        for (int half = 0; half < 2; half++) {
            int grow = half ? rB : rA;
            if (grow < NN) {
                float* yr = Y + (size_t)grow * 64;
                float* ar = AGG + (size_t)grow * 64;
#pragma unroll
                for (int nt = 0; nt < 8; nt++) {
                    float v0 = acc[nt][half * 2 + 0];
                    float v1 = acc[nt][half * 2 + 1];
                    int c = nt * 8 + cb;
                    *(float2*)(yr + c) = make_float2(v0, v1);
                    *(float2*)(ar + c) = make_float2(fmaf(v0, ep, bb[c]), fmaf(v1, ep, bb[c + 1]));
                }
            }
        }
    } else {
        float ps[8][2], pq[8][2];
#pragma unroll
        for (int nt = 0; nt < 8; nt++) {
            ps[nt][0] = ps[nt][1] = 0.f;
            pq[nt][0] = pq[nt][1] = 0.f;
        }
#pragma unroll
        for (int half = 0; half < 2; half++) {
            int grow = half ? rB : rA;
            bool valid = (grow < NN);
            float* yr = Y + (size_t)grow * 64;
#pragma unroll
            for (int nt = 0; nt < 8; nt++) {
                int c = nt * 8 + cb;
                float u0 = 0.f, u1 = 0.f;
                if (valid) {
                    u0 = fmaxf(acc[nt][half * 2 + 0] + bb[c], 0.f);
                    u1 = fmaxf(acc[nt][half * 2 + 1] + bb[c + 1], 0.f);
                    *(float2*)(yr + c) = make_float2(u0, u1);
                }
                ps[nt][0] += u0; ps[nt][1] += u1;
                pq[nt][0] += u0 * u0; pq[nt][1] += u1 * u1;
            }
        }
#pragma unroll
        for (int nt = 0; nt < 8; nt++) {
#pragma unroll
            for (int q = 0; q < 2; q++) {
#pragma unroll
                for (int o = 4; o <= 16; o <<= 1) {
                    ps[nt][q] += __shfl_xor_sync(0xffffffffu, ps[nt][q], o);
                    pq[nt][q] += __shfl_xor_sync(0xffffffffu, pq[nt][q], o);
                }
            }
        }
        if (lane < 4) {
#pragma unroll
            for (int nt = 0; nt < 8; nt++) {
                int c = nt * 8 + lane * 2;
                atomicAdd(&bsum[c], ps[nt][0]);
                atomicAdd(&bsum[c + 1], ps[nt][1]);
                atomicAdd(&bsq[c], pq[nt][0]);
                atomicAdd(&bsq[c + 1], pq[nt][1]);
            }
        }
        __syncthreads();
        if (tid < 64) {
            int bank = blockIdx.x & (NBANK - 1);
            atomicAdd(&g_sumB[bank][tid], (double)bsum[tid]);
            atomicAdd(&g_sqB[bank][tid], (double)bsq[tid]);
        }
    }
}

// ---------------- scatter-add over edges ----------------
__global__ __launch_bounds__(256) void scatter_kernel(const void* __restrict__ eiv)
{
    if (blockIdx.x == 0) {
        for (int i = threadIdx.x; i < NBANK * HH; i += 256) {
            ((double*)g_sumB)[i] = 0.0;
            ((double*)g_sqB)[i] = 0.0;
        }
    }
    int t = blockIdx.x * 256 + threadIdx.x;
    int e = t >> 4;
    int c = t & 15;
    if (e >= EE) return;
    int s, d;
    if (g_ei32) {
        const int* ei = (const int*)eiv;
        s = __ldg(ei + e);
        d = __ldg(ei + EE + e);
    } else {
        const long long* ei = (const long long*)eiv;
        s = (int)__ldg(ei + e);
        d = (int)__ldg(ei + EE + e);
    }
    float4 v = __ldg(((const float4*)g_y) + (size_t)s * 16 + c);
    float* p = g_agg + ((size_t)d * 64 + c * 4);
    asm volatile("red.global.add.v4.f32 [%0], {%1,%2,%3,%4};"
                 :: "l"(p), "f"(v.x), "f"(v.y), "f"(v.z), "f"(v.w)
                 : "memory");
}

// ---------------- final: out = bn_relu(u3) @ lin_w + lin_b ----------------
__global__ __launch_bounds__(128) void final_kernel(
    const float* __restrict__ bng, const float* __restrict__ bnb,
    const float* __restrict__ lw, const float* __restrict__ lb,
    float* __restrict__ out)
{
    __shared__ float a_sh[128 * 65];
    __shared__ float w_sh[64 * 10];
    __shared__ float b_sh[10];
    __shared__ float bnsc[64];
    __shared__ float bnsh[64];

    int tid = threadIdx.x;
    if (tid < 64) {
        double s = 0.0, q = 0.0;
#pragma unroll
        for (int b = 0; b < NBANK; b++) { s += g_sumB[b][tid]; q += g_sqB[b][tid]; }
        double m = s / (double)NN;
        double v = q / (double)NN - m * m;
        float sc = bng[tid] * rsqrtf((float)v + 1e-5f);
        bnsc[tid] = sc;
        bnsh[tid] = bnb[tid] - (float)m * sc;
    }
    for (int i = tid; i < 640; i += 128) w_sh[i] = lw[i];
    if (tid < 10) b_sh[tid] = lb[tid];
    __syncthreads();

    int row0 = blockIdx.x * 128;
    for (int idx = tid; idx < 128 * 64; idx += 128) {
        int r = idx >> 6;
        int k = idx & 63;
        int grow = row0 + r;
        float val = 0.f;
        if (grow < NN) val = g_u[(size_t)grow * 64 + k];
        a_sh[r * 65 + k] = fmaxf(fmaf(val, bnsc[k], bnsh[k]), 0.f);
    }
    __syncthreads();

    int grow = row0 + tid;
    if (grow < NN) {
        float a[64];
#pragma unroll
        for (int k = 0; k < 64; k++) a[k] = a_sh[tid * 65 + k];
        float accv[10];
#pragma unroll
        for (int c = 0; c < 10; c++) accv[c] = b_sh[c];
#pragma unroll
        for (int k = 0; k < 64; k++)
#pragma unroll
            for (int c = 0; c < 10; c++)
                accv[c] = fmaf(a[k], w_sh[k * 10 + c], accv[c]);
#pragma unroll
        for (int c = 0; c < 10; c++) out[(size_t)grow * 10 + c] = accv[c];
    }
}

// ---------------- launch ----------------
extern "C" void kernel_launch(void* const* d_in, const int* in_sizes, int n_in,
                              void* d_out, int out_size)
{
    const float* x       = (const float*)d_in[0];
    const void*  ei      = d_in[1];
    const float* eps1    = (const float*)d_in[2];
    const float* w1a     = (const float*)d_in[3];
    const float* b1a     = (const float*)d_in[4];
    const float* w1b     = (const float*)d_in[5];
    const float* b1b     = (const float*)d_in[6];
    const float* g1      = (const float*)d_in[7];
    const float* be1     = (const float*)d_in[8];
    const float* eps2    = (const float*)d_in[9];
    const float* w2a     = (const float*)d_in[10];
    const float* b2a     = (const float*)d_in[11];
    const float* w2b     = (const float*)d_in[12];
    const float* b2b     = (const float*)d_in[13];
    const float* g2      = (const float*)d_in[14];
    const float* be2     = (const float*)d_in[15];
    const float* eps3    = (const float*)d_in[16];
    const float* w3a     = (const float*)d_in[17];
    const float* b3a     = (const float*)d_in[18];
    const float* w3b     = (const float*)d_in[19];
    const float* b3b     = (const float*)d_in[20];
    const float* g3      = (const float*)d_in[21];
    const float* be3     = (const float*)d_in[22];
    const float* lin_w   = (const float*)d_in[23];
    const float* lin_b   = (const float*)d_in[24];
    float* out = (float*)d_out;

    float *yp = nullptr, *ap = nullptr, *up = nullptr;
    cudaGetSymbolAddress((void**)&yp, g_y);
    cudaGetSymbolAddress((void**)&ap, g_agg);
    cudaGetSymbolAddress((void**)&up, g_u);

    const int gemm_blocks = (NN + 127) / 128;          // 391
    const int scat_blocks = (EE * 16) / 256;           // 50000
    const int smem_bytes = 2 * 128 * 72 * 2 + 2 * 64 * 72 * 2;   // 55296 B

    static int attr_done = 0;
    if (!attr_done) {
        cudaFuncSetAttribute(tc_gemm<128, 0, 0>,
                             cudaFuncAttributeMaxDynamicSharedMemorySize, smem_bytes);
        cudaFuncSetAttribute(tc_gemm<64, 1, 1>,
                             cudaFuncAttributeMaxDynamicSharedMemorySize, smem_bytes);
        cudaFuncSetAttribute(tc_gemm<64, 2, 0>,
                             cudaFuncAttributeMaxDynamicSharedMemorySize, smem_bytes);
        attr_done = 1;
    }

    detect_dtype_kernel<<<1, 32>>>((const int*)ei);
    split_w_kernel<<<(WTOT + 255) / 256, 256>>>(w1a, w1b, w2a, w2b, w3a, w3b);

    // Weight offsets in g_whi/g_wlo
    const int OW1A = 0, OW1B = 8192, OW2A = 12288, OW2B = 16384, OW3A = 20480, OW3B = 24576;

    // ---- layer 1 ----
    tc_gemm<128, 0, 0><<<gemm_blocks, 256, smem_bytes>>>(x, OW1A, b1a, eps1, nullptr, nullptr, yp, ap);
    scatter_kernel<<<scat_blocks, 256>>>(ei);
    tc_gemm<64, 1, 1><<<gemm_blocks, 256, smem_bytes>>>(ap, OW1B, b1b, nullptr, nullptr, nullptr, up, nullptr);

    // ---- layer 2 ----
    tc_gemm<64, 2, 0><<<gemm_blocks, 256, smem_bytes>>>(up, OW2A, b2a, eps2, g1, be1, yp, ap);
    scatter_kernel<<<scat_blocks, 256>>>(ei);
    tc_gemm<64, 1, 1><<<gemm_blocks, 256, smem_bytes>>>(ap, OW2B, b2b, nullptr, nullptr, nullptr, up, nullptr);

    // ---- layer 3 ----
    tc_gemm<64, 2, 0><<<gemm_blocks, 256, smem_bytes>>>(up, OW3A, b3a, eps3, g2, be2, yp, ap);
    scatter_kernel<<<scat_blocks, 256>>>(ei);
    tc_gemm<64, 1, 1><<<gemm_blocks, 256, smem_bytes>>>(ap, OW3B, b3b, nullptr, nullptr, nullptr, up, nullptr);

    // ---- classifier ----
    final_kernel<<<(NN + 127) / 128, 128>>>(g3, be3, lin_w, lin_b, out);
}